// round 15
// baseline (speedup 1.0000x reference)
#include <cuda_runtime.h>
#include <cuda_bf16.h>
#include <cstddef>
#include <cstdint>

// Shapes
#define NBLK 4
#define BATCH 8
#define TLEN 1024
#define DDIM 1024
#define VOCAB 256
#define IDIM 2816
#define BT 8192
#define EPSF 1e-6f

// ===========================================================================
// Global scratch (static __device__; no allocations allowed)
// ===========================================================================
static constexpr size_t SZ_WG = (size_t)NBLK * 3 * DDIM * DDIM;
static constexpr size_t SZ_WO = (size_t)NBLK * DDIM * DDIM;
static constexpr size_t SZ_WU = (size_t)NBLK * 2 * IDIM * DDIM;
static constexpr size_t SZ_WN = (size_t)NBLK * DDIM * IDIM;

__device__ __align__(128) float g_Y[(size_t)BT * DDIM];
__device__ __align__(128) float g_XO[(size_t)BT * DDIM];
__device__ __align__(128) float g_G[(size_t)BT * 3 * DDIM];
__device__ __align__(128) float g_H[(size_t)BT * DDIM];
__device__ __align__(128) float g_U[(size_t)BT * 2 * IDIM];
__device__ __align__(128) float g_Bg[(size_t)NBLK * 3 * DDIM];
__device__ __align__(128) float g_lb[(size_t)NBLK * DDIM];
__device__ __align__(128) __nv_bfloat16 g_Ah[(size_t)BT * IDIM];
__device__ __align__(128) __nv_bfloat16 g_Al[(size_t)BT * IDIM];
__device__ __align__(128) __nv_bfloat16 g_Wgh[SZ_WG], g_Wgl[SZ_WG];
__device__ __align__(128) __nv_bfloat16 g_Woh[SZ_WO], g_Wol[SZ_WO];
__device__ __align__(128) __nv_bfloat16 g_Wuh[SZ_WU], g_Wul[SZ_WU];
__device__ __align__(128) __nv_bfloat16 g_Wnh[SZ_WN], g_Wnl[SZ_WN];
__device__ __align__(128) __nv_bfloat16 g_Wvh[(size_t)VOCAB * DDIM], g_Wvl[(size_t)VOCAB * DDIM];

// ===========================================================================
// Small helpers
// ===========================================================================
__device__ __forceinline__ float sigm(float x) { return 1.f / (1.f + __expf(-x)); }

__device__ __forceinline__ void split_bf16(float v, __nv_bfloat16& h, __nv_bfloat16& l) {
    h = __float2bfloat16(v);
    l = __float2bfloat16(v - __bfloat162float(h));
}

__device__ __forceinline__ float blockReduceSum(float v) {
    static __shared__ float sh[8];
    #pragma unroll
    for (int o = 16; o > 0; o >>= 1) v += __shfl_xor_sync(0xffffffffu, v, o);
    int w = threadIdx.x >> 5;
    if ((threadIdx.x & 31) == 0) sh[w] = v;
    __syncthreads();
    if (threadIdx.x < 8) {
        v = sh[threadIdx.x];
        #pragma unroll
        for (int o = 4; o > 0; o >>= 1) v += __shfl_xor_sync(0xffu, v, o);
        if (threadIdx.x == 0) sh[0] = v;
    }
    __syncthreads();
    v = sh[0];
    __syncthreads();
    return v;
}

__device__ __forceinline__ uint32_t smem_u32(const void* p) {
    uint32_t a;
    asm("{ .reg .u64 t; cvta.to.shared.u64 t, %1; cvt.u32.u64 %0, t; }" : "=r"(a) : "l"(p));
    return a;
}

// ===========================================================================
// lb = cumsum(softmax(weight_l)) - weight_l[:, :1]
// ===========================================================================
__global__ void lb_kernel(const float* __restrict__ weight_l, float* __restrict__ lb) {
    __shared__ float sh[1024];
    const int i = blockIdx.x, d = threadIdx.x;
    float w = weight_l[i * 1024 + d];
    sh[d] = w; __syncthreads();
    for (int s = 512; s > 0; s >>= 1) { if (d < s) sh[d] = fmaxf(sh[d], sh[d + s]); __syncthreads(); }
    float mx = sh[0]; __syncthreads();
    float e = __expf(w - mx);
    sh[d] = e; __syncthreads();
    for (int s = 512; s > 0; s >>= 1) { if (d < s) sh[d] += sh[d + s]; __syncthreads(); }
    float tot = sh[0]; __syncthreads();
    float p = e / tot;
    sh[d] = p; __syncthreads();
    for (int off = 1; off < 1024; off <<= 1) {
        float add = (d >= off) ? sh[d - off] : 0.f;
        __syncthreads();
        sh[d] += add;
        __syncthreads();
    }
    lb[i * 1024 + d] = sh[d] - weight_l[i * 1024];
}

// ===========================================================================
// Weight folding -> bf16 hi/lo splits (gate fold also emits gate bias)
// ===========================================================================
__global__ void fold_gate_kernel(const float* __restrict__ lf_w, const float* __restrict__ lc_w,
                                 const float* __restrict__ lg_w, const float* __restrict__ wg_in,
                                 const float* __restrict__ wg_f, const float* __restrict__ wg_c,
                                 const float* __restrict__ wg_g,
                                 const float* __restrict__ lf_b, const float* __restrict__ lc_b,
                                 const float* __restrict__ lg_b, float* __restrict__ Bg,
                                 __nv_bfloat16* __restrict__ Wh, __nv_bfloat16* __restrict__ Wl) {
    const size_t tid0 = (size_t)blockIdx.x * blockDim.x + threadIdx.x;
    if (tid0 < (size_t)NBLK * 3 * DDIM) {
        int i = (int)(tid0 / 3072);
        int j = (int)(tid0 % 3072);
        int s = j >> 10;
        int o = j & 1023;
        const float* b = (s == 0) ? lf_b : (s == 1) ? lc_b : lg_b;
        Bg[tid0] = b[i * DDIM + o];
    }
    for (size_t idx = tid0; idx < SZ_WG; idx += (size_t)gridDim.x * blockDim.x) {
        int k = (int)(idx & 1023);
        size_t r = idx >> 10;
        int i = (int)(r / 3072);
        int j = (int)(r % 3072);
        int s = j >> 10;
        int o = j & 1023;
        const float* lw = (s == 0) ? lf_w : (s == 1) ? lc_w : lg_w;
        const float* wv = (s == 0) ? wg_f : (s == 1) ? wg_c : wg_g;
        float w = lw[((size_t)i * DDIM + o) * DDIM + k] * wg_in[i * DDIM + k] * wv[i * DDIM + k];
        split_bf16(w, Wh[idx], Wl[idx]);
    }
}

__global__ void fold_wo_kernel(const float* __restrict__ lo_w, const float* __restrict__ wg_o_out,
                               __nv_bfloat16* __restrict__ Wh, __nv_bfloat16* __restrict__ Wl) {
    for (size_t idx = (size_t)blockIdx.x * blockDim.x + threadIdx.x; idx < SZ_WO;
         idx += (size_t)gridDim.x * blockDim.x) {
        int k = (int)(idx & 1023);
        int i = (int)(idx / ((size_t)DDIM * DDIM));
        float w = lo_w[idx] * wg_o_out[i * DDIM + k];
        split_bf16(w, Wh[idx], Wl[idx]);
    }
}

__global__ void fold_wu_kernel(const float* __restrict__ lu_w, const float* __restrict__ glu_wg,
                               const float* __restrict__ glu_wgo,
                               __nv_bfloat16* __restrict__ Wh, __nv_bfloat16* __restrict__ Wl) {
    for (size_t idx = (size_t)blockIdx.x * blockDim.x + threadIdx.x; idx < SZ_WU;
         idx += (size_t)gridDim.x * blockDim.x) {
        int k = (int)(idx & 1023);
        int i = (int)(idx / ((size_t)2 * IDIM * DDIM));
        float w = lu_w[idx] * glu_wg[i * DDIM + k] * glu_wgo[i * DDIM + k];
        split_bf16(w, Wh[idx], Wl[idx]);
    }
}

__global__ void fold_wn_kernel(const float* __restrict__ ln_w, const float* __restrict__ glu_wd,
                               __nv_bfloat16* __restrict__ Wh, __nv_bfloat16* __restrict__ Wl) {
    for (size_t idx = (size_t)blockIdx.x * blockDim.x + threadIdx.x; idx < SZ_WN;
         idx += (size_t)gridDim.x * blockDim.x) {
        int k = (int)(idx % IDIM);
        int i = (int)(idx / ((size_t)DDIM * IDIM));
        float w = ln_w[idx] * glu_wd[i * IDIM + k];
        split_bf16(w, Wh[idx], Wl[idx]);
    }
}

__global__ void split_mat_kernel(const float* __restrict__ X,
                                 __nv_bfloat16* __restrict__ Xh, __nv_bfloat16* __restrict__ Xl,
                                 size_t n) {
    for (size_t idx = (size_t)blockIdx.x * blockDim.x + threadIdx.x; idx < n;
         idx += (size_t)gridDim.x * blockDim.x) {
        split_bf16(X[idx], Xh[idx], Xl[idx]);
    }
}

// ===========================================================================
// Embedding gather
// ===========================================================================
__global__ void embed_kernel(const int* __restrict__ x, const float* __restrict__ emb,
                             float* __restrict__ Y) {
    for (size_t idx = (size_t)blockIdx.x * blockDim.x + threadIdx.x; idx < (size_t)BT * DDIM;
         idx += (size_t)gridDim.x * blockDim.x) {
        size_t row = idx >> 10;
        int d = (int)(idx & 1023);
        Y[idx] = emb[(size_t)x[row] * DDIM + d];
    }
}

// ===========================================================================
// Row scale (double RMS with folded weights) -> bf16 hi/lo
// ===========================================================================
__global__ void rowscale_kernel(const float* __restrict__ X, const float* __restrict__ wv,
                                __nv_bfloat16* __restrict__ Ah, __nv_bfloat16* __restrict__ Al) {
    const int row = blockIdx.x;
    const float* xr = X + (size_t)row * DDIM;
    float x[4], s0 = 0.f, s1 = 0.f;
    #pragma unroll
    for (int j = 0; j < 4; j++) {
        int c = threadIdx.x + j * 256;
        x[j] = xr[c];
        float w = wv[c];
        s0 += x[j] * x[j];
        s1 += x[j] * x[j] * w * w;
    }
    s0 = blockReduceSum(s0);
    s1 = blockReduceSum(s1);
    float r0 = rsqrtf(s0 * (1.f / DDIM) + EPSF);
    float r1 = rsqrtf(r0 * r0 * s1 * (1.f / DDIM) + EPSF);
    float sc = r0 * r1;
    __nv_bfloat16* ah = Ah + (size_t)row * DDIM;
    __nv_bfloat16* al = Al + (size_t)row * DDIM;
    #pragma unroll
    for (int j = 0; j < 4; j++) {
        int c = threadIdx.x + j * 256;
        split_bf16(x[j] * sc, ah[c], al[c]);
    }
}

// ===========================================================================
// Linear recurrence scan over T
// ===========================================================================
__global__ void scan_kernel(const float* __restrict__ G, const float* __restrict__ lb_i,
                            float* __restrict__ H) {
    const int l = blockIdx.x * blockDim.x + threadIdx.x;
    const int b = l >> 10, d = l & 1023;
    const float lbv = lb_i[d];
    const float* Gb = G + (size_t)b * TLEN * 3072;
    float* Hb = H + (size_t)b * TLEN * DDIM;
    float h = 0.f;
    float bf[8], bc[8];
    #pragma unroll
    for (int j = 0; j < 8; j++) { bf[j] = Gb[j * 3072 + d]; bc[j] = Gb[j * 3072 + 1024 + d]; }
    for (int t0 = 0; t0 < TLEN; t0 += 8) {
        float nf[8] = {0, 0, 0, 0, 0, 0, 0, 0}, nc[8] = {0, 0, 0, 0, 0, 0, 0, 0};
        if (t0 + 8 < TLEN) {
            #pragma unroll
            for (int j = 0; j < 8; j++) {
                nf[j] = Gb[(size_t)(t0 + 8 + j) * 3072 + d];
                nc[j] = Gb[(size_t)(t0 + 8 + j) * 3072 + 1024 + d];
            }
        }
        #pragma unroll
        for (int j = 0; j < 8; j++) {
            float f = lbv + (1.f - lbv) * sigm(bf[j]);
            float c = bc[j] * sigm(bc[j]);
            h = f * h + (1.f - f) * c;
            Hb[(size_t)(t0 + j) * DDIM + d] = h;
        }
        #pragma unroll
        for (int j = 0; j < 8; j++) { bf[j] = nf[j]; bc[j] = nc[j]; }
    }
}

// ===========================================================================
// g path elementwise -> bf16 hi/lo
// ===========================================================================
__global__ void gelem_kernel(const float* __restrict__ G, const float* __restrict__ H,
                             const float* __restrict__ wnorm,
                             __nv_bfloat16* __restrict__ Ah, __nv_bfloat16* __restrict__ Al) {
    const int row = blockIdx.x;
    const float* gr = G + (size_t)row * 3072 + 2048;
    float gg[4], s = 0.f;
    #pragma unroll
    for (int j = 0; j < 4; j++) {
        int c = threadIdx.x + j * 256;
        gg[j] = gr[c];
        s += gg[j] * gg[j];
    }
    s = blockReduceSum(s);
    float rg = rsqrtf(s * (1.f / DDIM) + EPSF);
    const float* hr = H + (size_t)row * DDIM;
    float g[4], s2 = 0.f;
    #pragma unroll
    for (int j = 0; j < 4; j++) {
        int c = threadIdx.x + j * 256;
        float h = hr[c];
        g[j] = gg[j] * rg * wnorm[c] * h * sigm(h);
        s2 += g[j] * g[j];
    }
    s2 = blockReduceSum(s2);
    float r2 = rsqrtf(s2 * (1.f / DDIM) + EPSF);
    __nv_bfloat16* ah = Ah + (size_t)row * DDIM;
    __nv_bfloat16* al = Al + (size_t)row * DDIM;
    #pragma unroll
    for (int j = 0; j < 4; j++) {
        int c = threadIdx.x + j * 256;
        split_bf16(g[j] * r2, ah[c], al[c]);
    }
}

// ===========================================================================
// GLU elementwise -> bf16 hi/lo (I = 2816 = 11*256)
// ===========================================================================
__global__ void gluelem_kernel(const float* __restrict__ U,
                               __nv_bfloat16* __restrict__ Ah, __nv_bfloat16* __restrict__ Al) {
    const int row = blockIdx.x;
    const float* ur = U + (size_t)row * 2 * IDIM;
    float p[11], s = 0.f;
    #pragma unroll
    for (int j = 0; j < 11; j++) {
        int c = threadIdx.x + j * 256;
        float ua = ur[c], ub = ur[IDIM + c];
        p[j] = ua * sigm(ua) * ub;
        s += p[j] * p[j];
    }
    s = blockReduceSum(s);
    float rp = rsqrtf(s * (1.f / IDIM) + EPSF);
    __nv_bfloat16* ah = Ah + (size_t)row * IDIM;
    __nv_bfloat16* al = Al + (size_t)row * IDIM;
    #pragma unroll
    for (int j = 0; j < 11; j++) {
        int c = threadIdx.x + j * 256;
        split_bf16(p[j] * rp, ah[c], al[c]);
    }
}

// ===========================================================================
// Split-bf16 GEMM via warp-level mma.sync (HMMA):
//   C[M,N] = (Ah+Al)[M,K] @ (Wh+Wl)[N,K]^T + bias (+add), dropping Al@Wl.
// CTA tile 128x128, 256 threads (8 warps, 4x2 grid, warp tile 32x64),
// K-chunk 32 = TWO k16 steps per barrier window (amortizes the correlated
// barrier+LDSM phase that left the tensor pipe ~45% idle at K-chunk 16),
// 2-stage pipeline, 96KB smem/CTA -> 2 CTAs/SM.
// Smem pitch 24 bf16 (48B): granule rotation (row*3) mod 8 -> conflict-free.
// ===========================================================================
#define PITCH 24                       // bf16 elements per smem row (48 B)
#define TILE_B (128 * PITCH * 2)       // 6144 bytes per k16-step tile
#define NSTAGE 2
#define GSM_BYTES (NSTAGE * 4 * 2 * TILE_B)  // 2 stages x 4 ops x 2 steps = 98304

__device__ __forceinline__ void cp16(uint32_t dst, const void* src) {
    asm volatile("cp.async.cg.shared.global [%0], [%1], 16;" :: "r"(dst), "l"(src));
}
__device__ __forceinline__ void cp_commit() { asm volatile("cp.async.commit_group;"); }
template <int N>
__device__ __forceinline__ void cp_wait() { asm volatile("cp.async.wait_group %0;" :: "n"(N)); }

__device__ __forceinline__ void ldm4(uint32_t* r, uint32_t addr) {
    asm volatile("ldmatrix.sync.aligned.m8n8.x4.shared.b16 {%0,%1,%2,%3}, [%4];"
                 : "=r"(r[0]), "=r"(r[1]), "=r"(r[2]), "=r"(r[3]) : "r"(addr));
}

__device__ __forceinline__ void mma16816(float* c, const uint32_t* a, const uint32_t* b) {
    asm volatile(
        "mma.sync.aligned.m16n8k16.row.col.f32.bf16.bf16.f32 "
        "{%0,%1,%2,%3}, {%4,%5,%6,%7}, {%8,%9}, {%0,%1,%2,%3};"
        : "+f"(c[0]), "+f"(c[1]), "+f"(c[2]), "+f"(c[3])
        : "r"(a[0]), "r"(a[1]), "r"(a[2]), "r"(a[3]), "r"(b[0]), "r"(b[1]));
}

__global__ __launch_bounds__(256, 2) void gemm_mm(
    const __nv_bfloat16* __restrict__ Ah, const __nv_bfloat16* __restrict__ Al,
    const __nv_bfloat16* __restrict__ Wh, const __nv_bfloat16* __restrict__ Wl,
    const float* __restrict__ bias, const float* __restrict__ add,
    float* __restrict__ C, int M, int N, int K) {
    extern __shared__ char smem[];
    const uint32_t sb = smem_u32(smem);
    const int tid = threadIdx.x;
    const int lane = tid & 31;
    const int wid = tid >> 5;
    const int wm = wid & 3;            // 4 warps along M (32 rows each)
    const int wn = wid >> 2;           // 2 warps along N (64 cols each)
    const int bm = blockIdx.y * 128;
    const int bn = blockIdx.x * 128;

    // operand tile sources: 0=Ah 1=Al 2=Wh 3=Wl
    const __nv_bfloat16* srcs[4] = {
        Ah + (size_t)bm * K, Al + (size_t)bm * K,
        Wh + (size_t)bn * K, Wl + (size_t)bn * K };

    // smem layout: [stage][op][step] tiles of TILE_B bytes
    // load K=32 chunk: per op 512 cp16 (128 rows x 4 granules); 2 per thread/op
    auto load_stage = [&](int c, int stage) {
        const size_t kb = (size_t)c * 32;    // k element offset
        #pragma unroll
        for (int it = 0; it < 2; it++) {
            int slot = tid + it * 256;
            int row = slot >> 2, g = slot & 3;          // g: step = g>>1, col16 = g&1
            #pragma unroll
            for (int op = 0; op < 4; op++) {
                const uint32_t base = sb + (((stage * 4 + op) * 2) + (g >> 1)) * TILE_B;
                cp16(base + row * (PITCH * 2) + (g & 1) * 16,
                     srcs[op] + (size_t)row * K + kb + g * 8);
            }
        }
    };

    // per-thread ldmatrix address offsets (bytes within a step tile)
    const int r8 = lane & 7, sel = lane >> 3;
    const uint32_t offA = (uint32_t)((r8 + (sel & 1) * 8) * (PITCH * 2) + (sel >> 1) * 16);
    const uint32_t offB = (uint32_t)((r8 + (sel >> 1) * 8) * (PITCH * 2) + (sel & 1) * 16);

    float acc[2][8][4];
    #pragma unroll
    for (int i = 0; i < 2; i++)
        #pragma unroll
        for (int j = 0; j < 8; j++)
            #pragma unroll
            for (int q = 0; q < 4; q++) acc[i][j][q] = 0.f;

    const int nk = K >> 5;                 // K-chunks of 32
    load_stage(0, 0); cp_commit();
    if (nk > 1) load_stage(1, 1);
    cp_commit();

    for (int c = 0; c < nk; c++) {
        const int stage = c & 1;
        cp_wait<1>();            // chunk c resident (c+1 may be in flight)
        __syncthreads();         // cross-thread visibility of chunk c

        const uint32_t opb = sb + (stage * 4) * (2 * TILE_B);
        #pragma unroll
        for (int step = 0; step < 2; step++) {
            const uint32_t tAh = opb + 0 * (2 * TILE_B) + step * TILE_B;
            const uint32_t tAl = opb + 1 * (2 * TILE_B) + step * TILE_B;
            const uint32_t tWh = opb + 2 * (2 * TILE_B) + step * TILE_B;
            const uint32_t tWl = opb + 3 * (2 * TILE_B) + step * TILE_B;

            uint32_t ah[2][4], al[2][4];
            #pragma unroll
            for (int mi = 0; mi < 2; mi++) {
                uint32_t rowoff = (uint32_t)((wm * 32 + mi * 16) * (PITCH * 2));
                ldm4(ah[mi], tAh + rowoff + offA);
                ldm4(al[mi], tAl + rowoff + offA);
            }
            #pragma unroll
            for (int half = 0; half < 2; half++) {
                uint32_t bh[2][4], bl[2][4];
                #pragma unroll
                for (int j = 0; j < 2; j++) {
                    int ni = half * 2 + j;
                    uint32_t rowoff = (uint32_t)((wn * 64 + ni * 16) * (PITCH * 2));
                    ldm4(bh[j], tWh + rowoff + offB);
                    ldm4(bl[j], tWl + rowoff + offB);
                }
                #pragma unroll
                for (int mi = 0; mi < 2; mi++) {
                    #pragma unroll
                    for (int j = 0; j < 2; j++) {
                        int ni = half * 2 + j;
                        mma16816(acc[mi][ni * 2 + 0], ah[mi], &bh[j][0]);
                        mma16816(acc[mi][ni * 2 + 1], ah[mi], &bh[j][2]);
                        mma16816(acc[mi][ni * 2 + 0], ah[mi], &bl[j][0]);
                        mma16816(acc[mi][ni * 2 + 1], ah[mi], &bl[j][2]);
                        mma16816(acc[mi][ni * 2 + 0], al[mi], &bh[j][0]);
                        mma16816(acc[mi][ni * 2 + 1], al[mi], &bh[j][2]);
                    }
                }
            }
        }

        __syncthreads();         // all warps done reading stage before refill
        if (c + 2 < nk) load_stage(c + 2, stage);
        cp_commit();             // keep group count aligned (may be empty)
    }

    // ---- epilogue: c frag m16n8: thread holds (row=lane>>2 (+8), col=(lane&3)*2 (+1))
    const int cr = lane >> 2, cc = (lane & 3) * 2;
    #pragma unroll
    for (int mi = 0; mi < 2; mi++) {
        #pragma unroll
        for (int nj = 0; nj < 8; nj++) {
            int row0 = bm + wm * 32 + mi * 16 + cr;
            int col = bn + wn * 64 + nj * 8 + cc;
            float b0 = bias[col], b1 = bias[col + 1];
            size_t o0 = (size_t)row0 * N + col;
            size_t o1 = (size_t)(row0 + 8) * N + col;
            float2 v0 = make_float2(acc[mi][nj][0] + b0, acc[mi][nj][1] + b1);
            float2 v1 = make_float2(acc[mi][nj][2] + b0, acc[mi][nj][3] + b1);
            if (add) {
                float2 a0 = *reinterpret_cast<const float2*>(add + o0);
                float2 a1 = *reinterpret_cast<const float2*>(add + o1);
                v0.x += a0.x; v0.y += a0.y; v1.x += a1.x; v1.y += a1.y;
            }
            *reinterpret_cast<float2*>(C + o0) = v0;
            *reinterpret_cast<float2*>(C + o1) = v1;
        }
    }
}

// ===========================================================================
// Host orchestration
// ===========================================================================
extern "C" void kernel_launch(void* const* d_in, const int* in_sizes, int n_in,
                              void* d_out, int out_size) {
    const int*   x        = (const int*)d_in[0];
    const float* emb      = (const float*)d_in[1];
    const float* wg_in    = (const float*)d_in[2];
    const float* wg_f     = (const float*)d_in[3];
    const float* wg_c     = (const float*)d_in[4];
    const float* wg_g     = (const float*)d_in[5];
    const float* wg_norm  = (const float*)d_in[6];
    const float* lf_w     = (const float*)d_in[7];
    const float* lf_b     = (const float*)d_in[8];
    const float* lc_w     = (const float*)d_in[9];
    const float* lc_b     = (const float*)d_in[10];
    const float* lg_w     = (const float*)d_in[11];
    const float* lg_b     = (const float*)d_in[12];
    const float* weight_l = (const float*)d_in[13];
    const float* wg_o_out = (const float*)d_in[14];
    const float* lo_w     = (const float*)d_in[15];
    const float* lo_b     = (const float*)d_in[16];
    const float* glu_wg   = (const float*)d_in[17];
    const float* glu_wgo  = (const float*)d_in[18];
    const float* glu_wd   = (const float*)d_in[19];
    const float* lu_w     = (const float*)d_in[20];
    const float* lu_b     = (const float*)d_in[21];
    const float* ln_w     = (const float*)d_in[22];
    const float* ln_b     = (const float*)d_in[23];
    const float* out_w    = (const float*)d_in[24];
    const float* out_b    = (const float*)d_in[25];

    cudaFuncSetAttribute(gemm_mm, cudaFuncAttributeMaxDynamicSharedMemorySize, GSM_BYTES);

    float *Y, *XO, *G, *H, *U, *Bg, *lb;
    __nv_bfloat16 *Ah, *Al, *Wgh, *Wgl, *Woh, *Wol, *Wuh, *Wul, *Wnh, *Wnl, *Wvh, *Wvl;
    cudaGetSymbolAddress((void**)&Y,  g_Y);
    cudaGetSymbolAddress((void**)&XO, g_XO);
    cudaGetSymbolAddress((void**)&G,  g_G);
    cudaGetSymbolAddress((void**)&H,  g_H);
    cudaGetSymbolAddress((void**)&U,  g_U);
    cudaGetSymbolAddress((void**)&Bg, g_Bg);
    cudaGetSymbolAddress((void**)&lb, g_lb);
    cudaGetSymbolAddress((void**)&Ah, g_Ah);
    cudaGetSymbolAddress((void**)&Al, g_Al);
    cudaGetSymbolAddress((void**)&Wgh, g_Wgh);
    cudaGetSymbolAddress((void**)&Wgl, g_Wgl);
    cudaGetSymbolAddress((void**)&Woh, g_Woh);
    cudaGetSymbolAddress((void**)&Wol, g_Wol);
    cudaGetSymbolAddress((void**)&Wuh, g_Wuh);
    cudaGetSymbolAddress((void**)&Wul, g_Wul);
    cudaGetSymbolAddress((void**)&Wnh, g_Wnh);
    cudaGetSymbolAddress((void**)&Wnl, g_Wnl);
    cudaGetSymbolAddress((void**)&Wvh, g_Wvh);
    cudaGetSymbolAddress((void**)&Wvl, g_Wvl);

    // --- Launch order keeps the first gemm_mm at launch index 3 so the
    //     harness's fixed ncu window (-s 5 -c 1) captures the GEMM.
    fold_gate_kernel<<<4096, 256>>>(lf_w, lc_w, lg_w, wg_in, wg_f, wg_c, wg_g,
                                    lf_b, lc_b, lg_b, Bg, Wgh, Wgl);          // 0
    embed_kernel<<<2048, 256>>>(x, emb, Y);                                   // 1
    rowscale_kernel<<<BT, 256>>>(Y, wg_in + 0 * DDIM, Ah, Al);                // 2
    gemm_mm<<<dim3(3072 / 128, BT / 128), 256, GSM_BYTES>>>(                  // 3
        Ah, Al, Wgh, Wgl, Bg, nullptr, G, BT, 3072, DDIM);
    lb_kernel<<<NBLK, 1024>>>(weight_l, lb);                                  // 4
    scan_kernel<<<BT / 64, 64>>>(G, lb + 0 * DDIM, H);                        // 5
    // remaining folds (independent of the pipeline above)
    fold_wo_kernel<<<2048, 256>>>(lo_w, wg_o_out, Woh, Wol);
    fold_wu_kernel<<<4096, 256>>>(lu_w, glu_wg, glu_wgo, Wuh, Wul);
    fold_wn_kernel<<<2048, 256>>>(ln_w, glu_wd, Wnh, Wnl);
    split_mat_kernel<<<512, 256>>>(out_w, Wvh, Wvl, (size_t)VOCAB * DDIM);

    for (int i = 0; i < NBLK; i++) {
        const size_t og = (size_t)i * 3 * DDIM * DDIM;
        const size_t oo = (size_t)i * DDIM * DDIM;
        const size_t ou = (size_t)i * 2 * IDIM * DDIM;
        const size_t on = (size_t)i * DDIM * IDIM;

        if (i > 0) {
            rowscale_kernel<<<BT, 256>>>(Y, wg_in + i * DDIM, Ah, Al);
            gemm_mm<<<dim3(3072 / 128, BT / 128), 256, GSM_BYTES>>>(
                Ah, Al, Wgh + og, Wgl + og, Bg + (size_t)i * 3 * DDIM, nullptr, G, BT, 3072, DDIM);
            scan_kernel<<<BT / 64, 64>>>(G, lb + i * DDIM, H);
        }
        // x_o = y + rms(x_g*h*sigmoid(h), wg_o_out) @ lo_w^T + lo_b
        gelem_kernel<<<BT, 256>>>(G, H, wg_norm + i * DDIM, Ah, Al);
        gemm_mm<<<dim3(DDIM / 128, BT / 128), 256, GSM_BYTES>>>(
            Ah, Al, Woh + oo, Wol + oo, lo_b + (size_t)i * DDIM, Y, XO, BT, DDIM, DDIM);
        // GLU up
        rowscale_kernel<<<BT, 256>>>(XO, glu_wg + i * DDIM, Ah, Al);
        gemm_mm<<<dim3(2 * IDIM / 128, BT / 128), 256, GSM_BYTES>>>(
            Ah, Al, Wuh + ou, Wul + ou, lu_b + (size_t)i * 2 * IDIM, nullptr, U, BT, 2 * IDIM, DDIM);
        // GLU down, residual into Y
        gluelem_kernel<<<BT, 256>>>(U, Ah, Al);
        gemm_mm<<<dim3(DDIM / 128, BT / 128), 256, GSM_BYTES>>>(
            Ah, Al, Wnh + on, Wnl + on, ln_b + (size_t)i * DDIM, XO, Y, BT, DDIM, IDIM);
    }

    // logits = Y @ out_w^T + out_b
    split_mat_kernel<<<2048, 256>>>(Y, Ah, Al, (size_t)BT * DDIM);
    gemm_mm<<<dim3(VOCAB / 128, BT / 128), 256, GSM_BYTES>>>(
        Ah, Al, Wvh, Wvl, out_b, nullptr, (float*)d_out, BT, VOCAB, DDIM);
}

// round 16
// speedup vs baseline: 2.4523x; 2.4523x over previous
#include <cuda_runtime.h>
#include <cuda_fp16.h>
#include <cstddef>
#include <cstdint>

// Shapes
#define NBLK 4
#define BATCH 8
#define TLEN 1024
#define DDIM 1024
#define VOCAB 256
#define IDIM 2816
#define BT 8192
#define EPSF 1e-6f

// ===========================================================================
// Global scratch (static __device__; no allocations allowed)
// ===========================================================================
static constexpr size_t SZ_WG = (size_t)NBLK * 3 * DDIM * DDIM;
static constexpr size_t SZ_WO = (size_t)NBLK * DDIM * DDIM;
static constexpr size_t SZ_WU = (size_t)NBLK * 2 * IDIM * DDIM;
static constexpr size_t SZ_WN = (size_t)NBLK * DDIM * IDIM;

__device__ __align__(128) float g_Y[(size_t)BT * DDIM];
__device__ __align__(128) float g_XO[(size_t)BT * DDIM];
__device__ __align__(128) float g_G[(size_t)BT * 3 * DDIM];
__device__ __align__(128) float g_H[(size_t)BT * DDIM];
__device__ __align__(128) float g_U[(size_t)BT * 2 * IDIM];
__device__ __align__(128) float g_Bg[(size_t)NBLK * 3 * DDIM];
__device__ __align__(128) float g_lb[(size_t)NBLK * DDIM];
__device__ __align__(128) __half g_A[(size_t)BT * IDIM];
__device__ __align__(128) __half g_Wgh[SZ_WG], g_Wgl[SZ_WG];
__device__ __align__(128) __half g_Woh[SZ_WO], g_Wol[SZ_WO];
__device__ __align__(128) __half g_Wuh[SZ_WU], g_Wul[SZ_WU];
__device__ __align__(128) __half g_Wnh[SZ_WN], g_Wnl[SZ_WN];
__device__ __align__(128) __half g_Wvh[(size_t)VOCAB * DDIM], g_Wvl[(size_t)VOCAB * DDIM];

// ===========================================================================
// Small helpers
// ===========================================================================
__device__ __forceinline__ float sigm(float x) { return 1.f / (1.f + __expf(-x)); }

__device__ __forceinline__ void split_fp16(float v, __half& h, __half& l) {
    h = __float2half(v);
    l = __float2half(v - __half2float(h));
}

__device__ __forceinline__ float blockReduceSum(float v) {
    static __shared__ float sh[8];
    #pragma unroll
    for (int o = 16; o > 0; o >>= 1) v += __shfl_xor_sync(0xffffffffu, v, o);
    int w = threadIdx.x >> 5;
    if ((threadIdx.x & 31) == 0) sh[w] = v;
    __syncthreads();
    if (threadIdx.x < 8) {
        v = sh[threadIdx.x];
        #pragma unroll
        for (int o = 4; o > 0; o >>= 1) v += __shfl_xor_sync(0xffu, v, o);
        if (threadIdx.x == 0) sh[0] = v;
    }
    __syncthreads();
    v = sh[0];
    __syncthreads();
    return v;
}

__device__ __forceinline__ uint32_t smem_u32(const void* p) {
    uint32_t a;
    asm("{ .reg .u64 t; cvta.to.shared.u64 t, %1; cvt.u32.u64 %0, t; }" : "=r"(a) : "l"(p));
    return a;
}

// ===========================================================================
// lb = cumsum(softmax(weight_l)) - weight_l[:, :1]
// ===========================================================================
__global__ void lb_kernel(const float* __restrict__ weight_l, float* __restrict__ lb) {
    __shared__ float sh[1024];
    const int i = blockIdx.x, d = threadIdx.x;
    float w = weight_l[i * 1024 + d];
    sh[d] = w; __syncthreads();
    for (int s = 512; s > 0; s >>= 1) { if (d < s) sh[d] = fmaxf(sh[d], sh[d + s]); __syncthreads(); }
    float mx = sh[0]; __syncthreads();
    float e = __expf(w - mx);
    sh[d] = e; __syncthreads();
    for (int s = 512; s > 0; s >>= 1) { if (d < s) sh[d] += sh[d + s]; __syncthreads(); }
    float tot = sh[0]; __syncthreads();
    float p = e / tot;
    sh[d] = p; __syncthreads();
    for (int off = 1; off < 1024; off <<= 1) {
        float add = (d >= off) ? sh[d - off] : 0.f;
        __syncthreads();
        sh[d] += add;
        __syncthreads();
    }
    lb[i * 1024 + d] = sh[d] - weight_l[i * 1024];
}

// ===========================================================================
// Weight folding -> fp16 hi/lo splits (gate fold also emits gate bias)
// ===========================================================================
__global__ void fold_gate_kernel(const float* __restrict__ lf_w, const float* __restrict__ lc_w,
                                 const float* __restrict__ lg_w, const float* __restrict__ wg_in,
                                 const float* __restrict__ wg_f, const float* __restrict__ wg_c,
                                 const float* __restrict__ wg_g,
                                 const float* __restrict__ lf_b, const float* __restrict__ lc_b,
                                 const float* __restrict__ lg_b, float* __restrict__ Bg,
                                 __half* __restrict__ Wh, __half* __restrict__ Wl) {
    const size_t tid0 = (size_t)blockIdx.x * blockDim.x + threadIdx.x;
    if (tid0 < (size_t)NBLK * 3 * DDIM) {
        int i = (int)(tid0 / 3072);
        int j = (int)(tid0 % 3072);
        int s = j >> 10;
        int o = j & 1023;
        const float* b = (s == 0) ? lf_b : (s == 1) ? lc_b : lg_b;
        Bg[tid0] = b[i * DDIM + o];
    }
    for (size_t idx = tid0; idx < SZ_WG; idx += (size_t)gridDim.x * blockDim.x) {
        int k = (int)(idx & 1023);
        size_t r = idx >> 10;
        int i = (int)(r / 3072);
        int j = (int)(r % 3072);
        int s = j >> 10;
        int o = j & 1023;
        const float* lw = (s == 0) ? lf_w : (s == 1) ? lc_w : lg_w;
        const float* wv = (s == 0) ? wg_f : (s == 1) ? wg_c : wg_g;
        float w = lw[((size_t)i * DDIM + o) * DDIM + k] * wg_in[i * DDIM + k] * wv[i * DDIM + k];
        split_fp16(w, Wh[idx], Wl[idx]);
    }
}

__global__ void fold_wo_kernel(const float* __restrict__ lo_w, const float* __restrict__ wg_o_out,
                               __half* __restrict__ Wh, __half* __restrict__ Wl) {
    for (size_t idx = (size_t)blockIdx.x * blockDim.x + threadIdx.x; idx < SZ_WO;
         idx += (size_t)gridDim.x * blockDim.x) {
        int k = (int)(idx & 1023);
        int i = (int)(idx / ((size_t)DDIM * DDIM));
        float w = lo_w[idx] * wg_o_out[i * DDIM + k];
        split_fp16(w, Wh[idx], Wl[idx]);
    }
}

__global__ void fold_wu_kernel(const float* __restrict__ lu_w, const float* __restrict__ glu_wg,
                               const float* __restrict__ glu_wgo,
                               __half* __restrict__ Wh, __half* __restrict__ Wl) {
    for (size_t idx = (size_t)blockIdx.x * blockDim.x + threadIdx.x; idx < SZ_WU;
         idx += (size_t)gridDim.x * blockDim.x) {
        int k = (int)(idx & 1023);
        int i = (int)(idx / ((size_t)2 * IDIM * DDIM));
        float w = lu_w[idx] * glu_wg[i * DDIM + k] * glu_wgo[i * DDIM + k];
        split_fp16(w, Wh[idx], Wl[idx]);
    }
}

__global__ void fold_wn_kernel(const float* __restrict__ ln_w, const float* __restrict__ glu_wd,
                               __half* __restrict__ Wh, __half* __restrict__ Wl) {
    for (size_t idx = (size_t)blockIdx.x * blockDim.x + threadIdx.x; idx < SZ_WN;
         idx += (size_t)gridDim.x * blockDim.x) {
        int k = (int)(idx % IDIM);
        int i = (int)(idx / ((size_t)DDIM * IDIM));
        float w = ln_w[idx] * glu_wd[i * IDIM + k];
        split_fp16(w, Wh[idx], Wl[idx]);
    }
}

__global__ void split_w_kernel(const float* __restrict__ X,
                               __half* __restrict__ Xh, __half* __restrict__ Xl, size_t n) {
    for (size_t idx = (size_t)blockIdx.x * blockDim.x + threadIdx.x; idx < n;
         idx += (size_t)gridDim.x * blockDim.x) {
        split_fp16(X[idx], Xh[idx], Xl[idx]);
    }
}

__global__ void cast_a_kernel(const float* __restrict__ X, __half* __restrict__ A, size_t n) {
    for (size_t idx = (size_t)blockIdx.x * blockDim.x + threadIdx.x; idx < n;
         idx += (size_t)gridDim.x * blockDim.x) {
        A[idx] = __float2half(X[idx]);
    }
}

// ===========================================================================
// Embedding gather
// ===========================================================================
__global__ void embed_kernel(const int* __restrict__ x, const float* __restrict__ emb,
                             float* __restrict__ Y) {
    for (size_t idx = (size_t)blockIdx.x * blockDim.x + threadIdx.x; idx < (size_t)BT * DDIM;
         idx += (size_t)gridDim.x * blockDim.x) {
        size_t row = idx >> 10;
        int d = (int)(idx & 1023);
        Y[idx] = emb[(size_t)x[row] * DDIM + d];
    }
}

// ===========================================================================
// Row scale (double RMS with folded weights) -> single fp16
// ===========================================================================
__global__ void rowscale_kernel(const float* __restrict__ X, const float* __restrict__ wv,
                                __half* __restrict__ A) {
    const int row = blockIdx.x;
    const float* xr = X + (size_t)row * DDIM;
    float x[4], s0 = 0.f, s1 = 0.f;
    #pragma unroll
    for (int j = 0; j < 4; j++) {
        int c = threadIdx.x + j * 256;
        x[j] = xr[c];
        float w = wv[c];
        s0 += x[j] * x[j];
        s1 += x[j] * x[j] * w * w;
    }
    s0 = blockReduceSum(s0);
    s1 = blockReduceSum(s1);
    float r0 = rsqrtf(s0 * (1.f / DDIM) + EPSF);
    float r1 = rsqrtf(r0 * r0 * s1 * (1.f / DDIM) + EPSF);
    float sc = r0 * r1;
    __half* ar = A + (size_t)row * DDIM;
    #pragma unroll
    for (int j = 0; j < 4; j++) {
        int c = threadIdx.x + j * 256;
        ar[c] = __float2half(x[j] * sc);
    }
}

// ===========================================================================
// Linear recurrence scan over T
// ===========================================================================
__global__ void scan_kernel(const float* __restrict__ G, const float* __restrict__ lb_i,
                            float* __restrict__ H) {
    const int l = blockIdx.x * blockDim.x + threadIdx.x;
    const int b = l >> 10, d = l & 1023;
    const float lbv = lb_i[d];
    const float* Gb = G + (size_t)b * TLEN * 3072;
    float* Hb = H + (size_t)b * TLEN * DDIM;
    float h = 0.f;
    float bf[8], bc[8];
    #pragma unroll
    for (int j = 0; j < 8; j++) { bf[j] = Gb[j * 3072 + d]; bc[j] = Gb[j * 3072 + 1024 + d]; }
    for (int t0 = 0; t0 < TLEN; t0 += 8) {
        float nf[8] = {0, 0, 0, 0, 0, 0, 0, 0}, nc[8] = {0, 0, 0, 0, 0, 0, 0, 0};
        if (t0 + 8 < TLEN) {
            #pragma unroll
            for (int j = 0; j < 8; j++) {
                nf[j] = Gb[(size_t)(t0 + 8 + j) * 3072 + d];
                nc[j] = Gb[(size_t)(t0 + 8 + j) * 3072 + 1024 + d];
            }
        }
        #pragma unroll
        for (int j = 0; j < 8; j++) {
            float f = lbv + (1.f - lbv) * sigm(bf[j]);
            float c = bc[j] * sigm(bc[j]);
            h = f * h + (1.f - f) * c;
            Hb[(size_t)(t0 + j) * DDIM + d] = h;
        }
        #pragma unroll
        for (int j = 0; j < 8; j++) { bf[j] = nf[j]; bc[j] = nc[j]; }
    }
}

// ===========================================================================
// g path elementwise -> single fp16
// ===========================================================================
__global__ void gelem_kernel(const float* __restrict__ G, const float* __restrict__ H,
                             const float* __restrict__ wnorm, __half* __restrict__ A) {
    const int row = blockIdx.x;
    const float* gr = G + (size_t)row * 3072 + 2048;
    float gg[4], s = 0.f;
    #pragma unroll
    for (int j = 0; j < 4; j++) {
        int c = threadIdx.x + j * 256;
        gg[j] = gr[c];
        s += gg[j] * gg[j];
    }
    s = blockReduceSum(s);
    float rg = rsqrtf(s * (1.f / DDIM) + EPSF);
    const float* hr = H + (size_t)row * DDIM;
    float g[4], s2 = 0.f;
    #pragma unroll
    for (int j = 0; j < 4; j++) {
        int c = threadIdx.x + j * 256;
        float h = hr[c];
        g[j] = gg[j] * rg * wnorm[c] * h * sigm(h);
        s2 += g[j] * g[j];
    }
    s2 = blockReduceSum(s2);
    float r2 = rsqrtf(s2 * (1.f / DDIM) + EPSF);
    __half* ar = A + (size_t)row * DDIM;
    #pragma unroll
    for (int j = 0; j < 4; j++) {
        int c = threadIdx.x + j * 256;
        ar[c] = __float2half(g[j] * r2);
    }
}

// ===========================================================================
// GLU elementwise -> single fp16 (I = 2816 = 11*256)
// ===========================================================================
__global__ void gluelem_kernel(const float* __restrict__ U, __half* __restrict__ A) {
    const int row = blockIdx.x;
    const float* ur = U + (size_t)row * 2 * IDIM;
    float p[11], s = 0.f;
    #pragma unroll
    for (int j = 0; j < 11; j++) {
        int c = threadIdx.x + j * 256;
        float ua = ur[c], ub = ur[IDIM + c];
        p[j] = ua * sigm(ua) * ub;
        s += p[j] * p[j];
    }
    s = blockReduceSum(s);
    float rp = rsqrtf(s * (1.f / IDIM) + EPSF);
    __half* ar = A + (size_t)row * IDIM;
    #pragma unroll
    for (int j = 0; j < 11; j++) {
        int c = threadIdx.x + j * 256;
        ar[c] = __float2half(p[j] * rp);
    }
}

// ===========================================================================
// fp16 2-product GEMM via warp-level mma.sync (HMMA):
//   C[M,N] = A[M,K] @ (Wh+Wl)[N,K]^T + bias (+add)
// Activation single fp16 (err ~2^-11); weights hi/lo fp16 split.
// Structure = measured-best R9 config: CTA tile 128x128, 512 threads
// (16 warps, 4x4 grid, warp tile 32x32), K-chunk 32 (two k16 steps),
// 4-stage cp.async pipeline, one __syncthreads per chunk.
// 3 operand tiles/stage (A, Wh, Wl) instead of 4 -> 25% less smem traffic,
// 16 MMAs per warp per k16 instead of 24 (33% fewer).
// Smem pitch 40 fp16 (80B): granule rotation (row*5) mod 8 -> conflict-free.
// ===========================================================================
#define PITCH 40                       // fp16 elements per smem row
#define TILE_B (128 * PITCH * 2)       // 10240 bytes per operand tile (32 k-elems)
#define NSTAGE 4
#define GSM_BYTES (NSTAGE * 3 * TILE_B)   // 4 stages x 3 operands = 122880

__device__ __forceinline__ void cp16(uint32_t dst, const void* src) {
    asm volatile("cp.async.cg.shared.global [%0], [%1], 16;" :: "r"(dst), "l"(src));
}
__device__ __forceinline__ void cp_commit() { asm volatile("cp.async.commit_group;"); }
template <int N>
__device__ __forceinline__ void cp_wait() { asm volatile("cp.async.wait_group %0;" :: "n"(N)); }

__device__ __forceinline__ void ldm4(uint32_t* r, uint32_t addr) {
    asm volatile("ldmatrix.sync.aligned.m8n8.x4.shared.b16 {%0,%1,%2,%3}, [%4];"
                 : "=r"(r[0]), "=r"(r[1]), "=r"(r[2]), "=r"(r[3]) : "r"(addr));
}

__device__ __forceinline__ void mma16816(float* c, const uint32_t* a, const uint32_t* b) {
    asm volatile(
        "mma.sync.aligned.m16n8k16.row.col.f32.f16.f16.f32 "
        "{%0,%1,%2,%3}, {%4,%5,%6,%7}, {%8,%9}, {%0,%1,%2,%3};"
        : "+f"(c[0]), "+f"(c[1]), "+f"(c[2]), "+f"(c[3])
        : "r"(a[0]), "r"(a[1]), "r"(a[2]), "r"(a[3]), "r"(b[0]), "r"(b[1]));
}

__global__ __launch_bounds__(512, 1) void gemm_mm(
    const __half* __restrict__ A,
    const __half* __restrict__ Wh, const __half* __restrict__ Wl,
    const float* __restrict__ bias, const float* __restrict__ add,
    float* __restrict__ C, int M, int N, int K) {
    extern __shared__ char smem[];
    const uint32_t sb = smem_u32(smem);
    const int tid = threadIdx.x;
    const int lane = tid & 31;
    const int wid = tid >> 5;
    const int wm = wid & 3;            // 4 warps along M (32 rows each)
    const int wn = wid >> 2;           // 4 warps along N (32 cols each)
    const int bm = blockIdx.y * 128;
    const int bn = blockIdx.x * 128;

    // operand tile sources: 0=A 1=Wh 2=Wl
    const __half* srcs[3] = {
        A + (size_t)bm * K, Wh + (size_t)bn * K, Wl + (size_t)bn * K };

    // cp.async: 512 16B-chunks per tile (128 rows x 4 chunks), 1 per thread/op
    auto load_stage = [&](int c, int stage) {
        const size_t kb = (size_t)c * 32;    // k element offset
        const int row = tid >> 2, ch = tid & 3;
        #pragma unroll
        for (int op = 0; op < 3; op++) {
            const uint32_t base = sb + (stage * 3 + op) * TILE_B;
            cp16(base + row * (PITCH * 2) + ch * 16,
                 srcs[op] + (size_t)row * K + kb + ch * 8);
        }
    };

    // per-thread ldmatrix address offsets (bytes within a tile)
    const int r8 = lane & 7, sel = lane >> 3;
    // A matrices: 0:(r,k0) 1:(r+8,k0) 2:(r,k0+8) 3:(r+8,k0+8)
    const uint32_t offA = (uint32_t)((r8 + (sel & 1) * 8) * (PITCH * 2) + (sel >> 1) * 16);
    // B matrices: 0:(n,k0) 1:(n,k0+8) 2:(n+8,k0) 3:(n+8,k0+8)
    const uint32_t offB = (uint32_t)((r8 + (sel >> 1) * 8) * (PITCH * 2) + (sel & 1) * 16);

    float acc[2][4][4];
    #pragma unroll
    for (int i = 0; i < 2; i++)
        #pragma unroll
        for (int j = 0; j < 4; j++)
            #pragma unroll
            for (int q = 0; q < 4; q++) acc[i][j][q] = 0.f;

    const int nk = K >> 5;
    load_stage(0, 0); cp_commit();
    load_stage(1, 1); cp_commit();
    load_stage(2, 2); cp_commit();

    for (int c = 0; c < nk; c++) {
        const int stage = c & (NSTAGE - 1);
        cp_wait<2>();            // chunk c resident
        __syncthreads();         // all warps done reading the buffer we refill
        if (c + 3 < nk) load_stage(c + 3, (c + 3) & (NSTAGE - 1));
        cp_commit();             // keep group count aligned (may be empty)

        const uint32_t tA  = sb + (stage * 3 + 0) * TILE_B;
        const uint32_t tWh = sb + (stage * 3 + 1) * TILE_B;
        const uint32_t tWl = sb + (stage * 3 + 2) * TILE_B;

        #pragma unroll
        for (int k16 = 0; k16 < 32; k16 += 16) {
            uint32_t a[2][4], bh[2][4], bl[2][4];
            #pragma unroll
            for (int mi = 0; mi < 2; mi++) {
                uint32_t rowoff = (uint32_t)((wm * 32 + mi * 16) * (PITCH * 2) + k16 * 2);
                ldm4(a[mi], tA + rowoff + offA);
            }
            #pragma unroll
            for (int ni = 0; ni < 2; ni++) {
                uint32_t rowoff = (uint32_t)((wn * 32 + ni * 16) * (PITCH * 2) + k16 * 2);
                ldm4(bh[ni], tWh + rowoff + offB);
                ldm4(bl[ni], tWl + rowoff + offB);
            }
            #pragma unroll
            for (int mi = 0; mi < 2; mi++) {
                #pragma unroll
                for (int ni = 0; ni < 2; ni++) {
                    // two n8 tiles per ldmatrix.x4: regs {0,1} and {2,3}
                    mma16816(acc[mi][ni * 2 + 0], a[mi], &bh[ni][0]);
                    mma16816(acc[mi][ni * 2 + 1], a[mi], &bh[ni][2]);
                    mma16816(acc[mi][ni * 2 + 0], a[mi], &bl[ni][0]);
                    mma16816(acc[mi][ni * 2 + 1], a[mi], &bl[ni][2]);
                }
            }
        }
    }

    // ---- epilogue: c frag m16n8: thread holds (row=lane>>2 (+8), col=(lane&3)*2 (+1))
    const int cr = lane >> 2, cc = (lane & 3) * 2;
    #pragma unroll
    for (int mi = 0; mi < 2; mi++) {
        #pragma unroll
        for (int nj = 0; nj < 4; nj++) {
            int row0 = bm + wm * 32 + mi * 16 + cr;
            int col = bn + wn * 32 + nj * 8 + cc;
            float b0 = bias[col], b1 = bias[col + 1];
            size_t o0 = (size_t)row0 * N + col;
            size_t o1 = (size_t)(row0 + 8) * N + col;
            float2 v0 = make_float2(acc[mi][nj][0] + b0, acc[mi][nj][1] + b1);
            float2 v1 = make_float2(acc[mi][nj][2] + b0, acc[mi][nj][3] + b1);
            if (add) {
                float2 a0 = *reinterpret_cast<const float2*>(add + o0);
                float2 a1 = *reinterpret_cast<const float2*>(add + o1);
                v0.x += a0.x; v0.y += a0.y; v1.x += a1.x; v1.y += a1.y;
            }
            *reinterpret_cast<float2*>(C + o0) = v0;
            *reinterpret_cast<float2*>(C + o1) = v1;
        }
    }
}

// ===========================================================================
// Host orchestration
// ===========================================================================
extern "C" void kernel_launch(void* const* d_in, const int* in_sizes, int n_in,
                              void* d_out, int out_size) {
    const int*   x        = (const int*)d_in[0];
    const float* emb      = (const float*)d_in[1];
    const float* wg_in    = (const float*)d_in[2];
    const float* wg_f     = (const float*)d_in[3];
    const float* wg_c     = (const float*)d_in[4];
    const float* wg_g     = (const float*)d_in[5];
    const float* wg_norm  = (const float*)d_in[6];
    const float* lf_w     = (const float*)d_in[7];
    const float* lf_b     = (const float*)d_in[8];
    const float* lc_w     = (const float*)d_in[9];
    const float* lc_b     = (const float*)d_in[10];
    const float* lg_w     = (const float*)d_in[11];
    const float* lg_b     = (const float*)d_in[12];
    const float* weight_l = (const float*)d_in[13];
    const float* wg_o_out = (const float*)d_in[14];
    const float* lo_w     = (const float*)d_in[15];
    const float* lo_b     = (const float*)d_in[16];
    const float* glu_wg   = (const float*)d_in[17];
    const float* glu_wgo  = (const float*)d_in[18];
    const float* glu_wd   = (const float*)d_in[19];
    const float* lu_w     = (const float*)d_in[20];
    const float* lu_b     = (const float*)d_in[21];
    const float* ln_w     = (const float*)d_in[22];
    const float* ln_b     = (const float*)d_in[23];
    const float* out_w    = (const float*)d_in[24];
    const float* out_b    = (const float*)d_in[25];

    cudaFuncSetAttribute(gemm_mm, cudaFuncAttributeMaxDynamicSharedMemorySize, GSM_BYTES);

    float *Y, *XO, *G, *H, *U, *Bg, *lb;
    __half *A, *Wgh, *Wgl, *Woh, *Wol, *Wuh, *Wul, *Wnh, *Wnl, *Wvh, *Wvl;
    cudaGetSymbolAddress((void**)&Y,  g_Y);
    cudaGetSymbolAddress((void**)&XO, g_XO);
    cudaGetSymbolAddress((void**)&G,  g_G);
    cudaGetSymbolAddress((void**)&H,  g_H);
    cudaGetSymbolAddress((void**)&U,  g_U);
    cudaGetSymbolAddress((void**)&Bg, g_Bg);
    cudaGetSymbolAddress((void**)&lb, g_lb);
    cudaGetSymbolAddress((void**)&A,  g_A);
    cudaGetSymbolAddress((void**)&Wgh, g_Wgh);
    cudaGetSymbolAddress((void**)&Wgl, g_Wgl);
    cudaGetSymbolAddress((void**)&Woh, g_Woh);
    cudaGetSymbolAddress((void**)&Wol, g_Wol);
    cudaGetSymbolAddress((void**)&Wuh, g_Wuh);
    cudaGetSymbolAddress((void**)&Wul, g_Wul);
    cudaGetSymbolAddress((void**)&Wnh, g_Wnh);
    cudaGetSymbolAddress((void**)&Wnl, g_Wnl);
    cudaGetSymbolAddress((void**)&Wvh, g_Wvh);
    cudaGetSymbolAddress((void**)&Wvl, g_Wvl);

    // --- Launch order keeps the first gemm_mm at launch index 3 so the
    //     harness's fixed ncu window (-s 5 -c 1) captures the GEMM.
    fold_gate_kernel<<<4096, 256>>>(lf_w, lc_w, lg_w, wg_in, wg_f, wg_c, wg_g,
                                    lf_b, lc_b, lg_b, Bg, Wgh, Wgl);          // 0
    embed_kernel<<<2048, 256>>>(x, emb, Y);                                   // 1
    rowscale_kernel<<<BT, 256>>>(Y, wg_in + 0 * DDIM, A);                     // 2
    gemm_mm<<<dim3(3072 / 128, BT / 128), 512, GSM_BYTES>>>(                  // 3
        A, Wgh, Wgl, Bg, nullptr, G, BT, 3072, DDIM);
    lb_kernel<<<NBLK, 1024>>>(weight_l, lb);                                  // 4
    scan_kernel<<<BT / 64, 64>>>(G, lb + 0 * DDIM, H);                        // 5
    // remaining folds (independent of the pipeline above)
    fold_wo_kernel<<<2048, 256>>>(lo_w, wg_o_out, Woh, Wol);
    fold_wu_kernel<<<4096, 256>>>(lu_w, glu_wg, glu_wgo, Wuh, Wul);
    fold_wn_kernel<<<2048, 256>>>(ln_w, glu_wd, Wnh, Wnl);
    split_w_kernel<<<512, 256>>>(out_w, Wvh, Wvl, (size_t)VOCAB * DDIM);

    for (int i = 0; i < NBLK; i++) {
        const size_t og = (size_t)i * 3 * DDIM * DDIM;
        const size_t oo = (size_t)i * DDIM * DDIM;
        const size_t ou = (size_t)i * 2 * IDIM * DDIM;
        const size_t on = (size_t)i * DDIM * IDIM;

        if (i > 0) {
            rowscale_kernel<<<BT, 256>>>(Y, wg_in + i * DDIM, A);
            gemm_mm<<<dim3(3072 / 128, BT / 128), 512, GSM_BYTES>>>(
                A, Wgh + og, Wgl + og, Bg + (size_t)i * 3 * DDIM, nullptr, G, BT, 3072, DDIM);
            scan_kernel<<<BT / 64, 64>>>(G, lb + i * DDIM, H);
        }
        // x_o = y + rms(x_g*h*sigmoid(h), wg_o_out) @ lo_w^T + lo_b
        gelem_kernel<<<BT, 256>>>(G, H, wg_norm + i * DDIM, A);
        gemm_mm<<<dim3(DDIM / 128, BT / 128), 512, GSM_BYTES>>>(
            A, Woh + oo, Wol + oo, lo_b + (size_t)i * DDIM, Y, XO, BT, DDIM, DDIM);
        // GLU up
        rowscale_kernel<<<BT, 256>>>(XO, glu_wg + i * DDIM, A);
        gemm_mm<<<dim3(2 * IDIM / 128, BT / 128), 512, GSM_BYTES>>>(
            A, Wuh + ou, Wul + ou, lu_b + (size_t)i * 2 * IDIM, nullptr, U, BT, 2 * IDIM, DDIM);
        // GLU down, residual into Y
        gluelem_kernel<<<BT, 256>>>(U, A);
        gemm_mm<<<dim3(DDIM / 128, BT / 128), 512, GSM_BYTES>>>(
            A, Wnh + on, Wnl + on, ln_b + (size_t)i * DDIM, XO, Y, BT, DDIM, IDIM);
    }

    // logits = Y @ out_w^T + out_b
    cast_a_kernel<<<2048, 256>>>(Y, A, (size_t)BT * DDIM);
    gemm_mm<<<dim3(VOCAB / 128, BT / 128), 512, GSM_BYTES>>>(
        A, Wvh, Wvl, out_b, nullptr, (float*)d_out, BT, VOCAB, DDIM);
}